// round 3
// baseline (speedup 1.0000x reference)
#include <cuda_runtime.h>

#define B_ROWS   8192
#define NBINS    125
#define M_CAND   4096
#define NTHREADS 256

// Scratch (no allocations allowed): per-row soft_min and validity.
__device__ float g_soft[B_ROWS];
__device__ float g_valid[B_ROWS];

__global__ __launch_bounds__(NTHREADS)
void softbin_row_kernel(const float* __restrict__ preds,
                        const float2* __restrict__ bin_coords,
                        const long long* __restrict__ x_vals,
                        const long long* __restrict__ bin_counts) {
    const int b   = blockIdx.x;
    const int tid = threadIdx.x;

    long long bin_id = x_vals[b * 3 + 0] * 25 + x_vals[b * 3 + 1] * 5 + x_vals[b * 3 + 2];
    if (bin_id < 0) bin_id = 0;
    if (bin_id >= NBINS) bin_id = NBINS - 1;
    int count = (int)bin_counts[bin_id];
    if (count > M_CAND) count = M_CAND;

    const float DEG2RAD = 0.017453292519943295f;
    const float lon1 = preds[b * 2 + 0] * DEG2RAD;
    const float lat1 = preds[b * 2 + 1] * DEG2RAD;
    const float cos_lat1 = __cosf(lat1);

    const float2* __restrict__ cand = bin_coords + (size_t)bin_id * M_CAND;

    // Online logsumexp of logits l = -dist/tau (tau = 0.25 -> l = -4*d)
    float m = -3.0e38f;
    float s = 0.0f;

    for (int j = tid; j < count; j += NTHREADS) {
        float2 c = __ldg(&cand[j]);            // (lon, lat)
        float lat2 = c.y * DEG2RAD;
        float lon2 = c.x * DEG2RAD;
        float sdlat = __sinf(0.5f * (lat2 - lat1));
        float sdlon = __sinf(0.5f * (lon2 - lon1));
        float a = fmaf(sdlat, sdlat, cos_lat1 * __cosf(lat2) * (sdlon * sdlon));
        a = __saturatef(a);
        // atan2(sqrt(a), sqrt(1-a)) == asin(sqrt(a)) for a in [0,1]
        float d = (2.0f * 3958.8f) * asinf(__fsqrt_rn(a));
        float l = -4.0f * d;                   // -d / tau

        if (l > m) {
            s = s * __expf(m - l) + 1.0f;
            m = l;
        } else {
            s += __expf(l - m);
        }
    }

    // Warp-level (m, s) pair combine
    #pragma unroll
    for (int off = 16; off > 0; off >>= 1) {
        float mo = __shfl_xor_sync(0xffffffffu, m, off);
        float so = __shfl_xor_sync(0xffffffffu, s, off);
        float mn = fmaxf(m, mo);
        s = s * __expf(m - mn) + so * __expf(mo - mn);
        m = mn;
    }

    __shared__ float sh_m[NTHREADS / 32];
    __shared__ float sh_s[NTHREADS / 32];
    const int warp = tid >> 5;
    const int lane = tid & 31;
    if (lane == 0) { sh_m[warp] = m; sh_s[warp] = s; }
    __syncthreads();

    if (tid == 0) {
        float M0 = sh_m[0], S0 = sh_s[0];
        #pragma unroll
        for (int w = 1; w < NTHREADS / 32; ++w) {
            float mo = sh_m[w], so = sh_s[w];
            float mn = fmaxf(M0, mo);
            S0 = S0 * __expf(M0 - mn) + so * __expf(mo - mn);
            M0 = mn;
        }
        float soft = 0.0f;
        if (count > 0) soft = -0.25f * (M0 + __logf(S0));
        g_soft[b]  = soft;
        g_valid[b] = (count > 0) ? 1.0f : 0.0f;
    }
}

__global__ __launch_bounds__(256)
void softbin_reduce_kernel(float* __restrict__ out) {
    __shared__ float sh[256];
    __shared__ float shv[256];
    const int tid = threadIdx.x;
    float s = 0.0f, v = 0.0f;
    for (int i = tid; i < B_ROWS; i += 256) {
        s += g_soft[i];
        v += g_valid[i];
    }
    sh[tid] = s;
    shv[tid] = v;
    __syncthreads();
    #pragma unroll
    for (int off = 128; off > 0; off >>= 1) {
        if (tid < off) {
            sh[tid]  += sh[tid + off];
            shv[tid] += shv[tid + off];
        }
        __syncthreads();
    }
    if (tid == 0) out[0] = sh[0] / fmaxf(shv[0], 1.0f);
}

extern "C" void kernel_launch(void* const* d_in, const int* in_sizes, int n_in,
                              void* d_out, int out_size) {
    // Identify inputs by element count (all four are distinct) — robust to
    // whatever ordering metadata.txt uses.
    const float*     preds      = 0;   // 8192*2   = 16384
    const float2*    bin_coords = 0;   // 125*4096*2 = 1024000
    const long long* x_vals     = 0;   // 8192*3   = 24576
    const long long* bin_counts = 0;   // 125
    for (int i = 0; i < n_in; ++i) {
        switch (in_sizes[i]) {
            case 16384:   preds      = (const float*)d_in[i];     break;
            case 1024000: bin_coords = (const float2*)d_in[i];    break;
            case 24576:   x_vals     = (const long long*)d_in[i]; break;
            case 125:     bin_counts = (const long long*)d_in[i]; break;
        }
    }
    float* out = (float*)d_out;

    softbin_row_kernel<<<B_ROWS, NTHREADS>>>(preds, bin_coords, x_vals, bin_counts);
    softbin_reduce_kernel<<<1, 256>>>(out);
}